// round 3
// baseline (speedup 1.0000x reference)
#include <cuda_runtime.h>
#include <cuda_bf16.h>
#include <math.h>

// Problem constants
#define BB   32
#define HH   14
#define WW   14
#define CC   32
#define KK   64
#define KS   5
#define OH   10
#define OW   10
#define PP   100      // OH*OW
#define NPOS 196      // H*W
#define MM   800      // KS*KS*C
#define IMG  6272     // NPOS*CC floats per batch
#define SIGB 1229312  // NPOS*NPOS*CC floats per batch of Sigma_in
#define SIGR 6304     // NPOS*CC + CC (diag row stride in floats)

// Scratch (device globals)
__device__ float2 g_wp [(MM/2) * KK];      // paired weights  {w[2m2][k], w[2m2+1][k]}
__device__ float2 g_wp2[(MM/2) * KK];      // paired squared weights
__device__ float  g_sp[KK];                // softplus(w_sigma)
__device__ float  g_dv[BB * PP * KK];      // diag_vals
__device__ float  g_G[BB * PP * PP];       // Gram matrices

// ---------------- f32x2 packed helpers ----------------
typedef unsigned long long ull;

__device__ __forceinline__ ull f2fma(ull a, ull b, ull c) {
    ull d;
    asm("fma.rn.f32x2 %0, %1, %2, %3;" : "=l"(d) : "l"(a), "l"(b), "l"(c));
    return d;
}
__device__ __forceinline__ float f2sum(ull v) {
    float lo, hi;
    asm("mov.b64 {%0, %1}, %2;" : "=f"(lo), "=f"(hi) : "l"(v));
    return lo + hi;
}

// ---------------- Kernel 1: tiny weight prep ----------------
// g_wp[m2*64+k] = {w[2m2][k], w[2m2+1][k]};  g_wp2 = elementwise square; g_sp = softplus.
__global__ __launch_bounds__(256) void k_prep_w(const float* __restrict__ w_mu,
                                                const float* __restrict__ w_sigma) {
    int idx = blockIdx.x * 256 + threadIdx.x;
    if (idx < 51200) {
        int m2 = idx >> 7;
        int r  = idx & 127;
        int k  = r >> 1;
        int s  = r & 1;
        ((float*)g_wp)[idx] = w_mu[(2 * m2 + s) * KK + k];
    } else if (idx < 102400) {
        int j  = idx - 51200;
        int m2 = j >> 7;
        int r  = j & 127;
        int k  = r >> 1;
        int s  = r & 1;
        float v = w_mu[(2 * m2 + s) * KK + k];
        ((float*)g_wp2)[j] = v * v;
    } else if (idx < 102464) {
        int k = idx - 102400;
        g_sp[k] = log1pf(expf(w_sigma[k]));
    }
}

// ---------------- Kernel 2: mu_out + diag_vals (fused Sigma-diag gather) ----------------
// grid (4 ptiles, 32 b), 256 threads.
// Warp w owns p_local in [w*4, w*4+4); each lane handles k = lane and lane+32.
__global__ __launch_bounds__(256) void k_mu_diag(const float* __restrict__ mu_in,
                                                 const float* __restrict__ Sg,
                                                 float* __restrict__ out_mu) {
    __shared__ __align__(16) float s_mu[7 * 14 * 32];   // 3136
    __shared__ __align__(16) float s_ds[7 * 14 * 32];   // 3136
    __shared__ float s_S[7 * 14];                       // per-pos channel sums
    __shared__ float s_tr[25];

    int tid  = threadIdx.x;
    int pt   = blockIdx.x;
    int b    = blockIdx.y;
    int r0   = (pt * 25) / 10;                // first image row of this tile
    int lane = tid & 31;
    int warp = tid >> 5;

    // --- load mu tile (coalesced float4) ---
    {
        const float4* src = reinterpret_cast<const float4*>(mu_in + b * IMG + r0 * 448);
        float4* dst = reinterpret_cast<float4*>(s_mu);
        #pragma unroll
        for (int it = 0; it < 4; it++) {
            int t = tid + it * 256;
            if (t < 784) dst[t] = src[t];
        }
    }

    // --- gather Sigma diagonal tile + fused channel-sum reduction ---
    {
        const float* sb = Sg + b * SIGB;
        float4* dst = reinterpret_cast<float4*>(s_ds);
        int c4 = tid & 7;                      // float4 index within channel dim
        #pragma unroll
        for (int it = 0; it < 4; it++) {
            int t = tid + it * 256;
            bool actv = (t < 784);
            int pos_l = t >> 3;                // local position 0..97
            float4 v = make_float4(0.f, 0.f, 0.f, 0.f);
            if (actv) {
                int pos = r0 * 14 + pos_l;
                v = *reinterpret_cast<const float4*>(sb + pos * SIGR + c4 * 4);
                dst[t] = v;
            }
            float part = v.x + v.y + v.z + v.w;
            part += __shfl_down_sync(0xffffffffu, part, 4, 8);
            part += __shfl_down_sync(0xffffffffu, part, 2, 8);
            part += __shfl_down_sync(0xffffffffu, part, 1, 8);
            if (actv && c4 == 0) s_S[pos_l] = part;
        }
    }
    __syncthreads();

    // --- trace per patch ---
    if (tid < 25) {
        int p  = pt * 25 + tid;
        int pr = p / 10 - r0, pc = p % 10;
        float s = 0.f;
        #pragma unroll
        for (int i = 0; i < KS; i++)
            #pragma unroll
            for (int j = 0; j < KS; j++)
                s += s_S[(pr + i) * 14 + pc + j];
        s_tr[tid] = s;
    }
    __syncthreads();

    // --- main GEMM: per warp 4 p's, per lane 2 k's ---
    int prr[4], pcc[4];
    bool act[4];
    #pragma unroll
    for (int jj = 0; jj < 4; jj++) {
        int pl = warp * 4 + jj;
        act[jj] = (pl < 25);
        int plc = act[jj] ? pl : 0;
        int p = pt * 25 + plc;
        prr[jj] = p / 10 - r0;
        pcc[jj] = p % 10;
    }

    ull accM[4][2], accV[4][2];
    #pragma unroll
    for (int jj = 0; jj < 4; jj++) {
        accM[jj][0] = 0ull; accM[jj][1] = 0ull;
        accV[jj][0] = 0ull; accV[jj][1] = 0ull;
    }

    const ull* wp  = reinterpret_cast<const ull*>(g_wp);
    const ull* wp2 = reinterpret_cast<const ull*>(g_wp2);

    #pragma unroll 1
    for (int ij = 0; ij < 25; ij++) {
        int i = ij / 5, j = ij % 5;
        int posl[4];
        #pragma unroll
        for (int jj = 0; jj < 4; jj++)
            posl[jj] = ((prr[jj] + i) * 14 + pcc[jj] + j) * 32;
        const ull* wr  = wp  + ij * 16 * 64 + lane;
        const ull* wr2 = wp2 + ij * 16 * 64 + lane;
        #pragma unroll
        for (int c2 = 0; c2 < 16; c2++) {
            ull w_lo  = __ldg(wr  + c2 * 64);
            ull w_hi  = __ldg(wr  + c2 * 64 + 32);
            ull ws_lo = __ldg(wr2 + c2 * 64);
            ull ws_hi = __ldg(wr2 + c2 * 64 + 32);
            #pragma unroll
            for (int jj = 0; jj < 4; jj++) {
                if (act[jj]) {
                    ull a = *reinterpret_cast<const ull*>(s_mu + posl[jj] + c2 * 2);
                    ull d = *reinterpret_cast<const ull*>(s_ds + posl[jj] + c2 * 2);
                    accM[jj][0] = f2fma(a, w_lo, accM[jj][0]);
                    accM[jj][1] = f2fma(a, w_hi, accM[jj][1]);
                    accV[jj][0] = f2fma(d, ws_lo, accV[jj][0]);
                    accV[jj][1] = f2fma(d, ws_hi, accV[jj][1]);
                }
            }
        }
    }

    float sp_lo = g_sp[lane];
    float sp_hi = g_sp[lane + 32];
    #pragma unroll
    for (int jj = 0; jj < 4; jj++) {
        if (act[jj]) {
            int pl = warp * 4 + jj;
            int p  = pt * 25 + pl;
            int base = (b * PP + p) * KK;
            float tr = s_tr[pl];
            out_mu[base + lane]      = f2sum(accM[jj][0]);
            out_mu[base + lane + 32] = f2sum(accM[jj][1]);
            g_dv[base + lane]        = f2sum(accV[jj][0]) + sp_lo * tr;
            g_dv[base + lane + 32]   = f2sum(accV[jj][1]) + sp_hi * tr;
        }
    }
}

// ---------------- Kernel 3: Gram via position-Gram factorization ----------------
#define SROW 198
#define YPAD 198
__global__ __launch_bounds__(256) void k_gram2(const float* __restrict__ mu_in) {
    extern __shared__ float sm[];
    float*  s_S  = sm;                                    // [196][SROW]
    float2* s_yc = (float2*)(sm + NPOS * SROW);           // [16 c2][YPAD pos]

    int tid = threadIdx.x;
    int b   = blockIdx.x;
    const float* mb = mu_in + b * IMG;

    for (int t = tid; t < 16 * NPOS; t += 256) {
        int c2 = t & 15, pos = t >> 4;
        s_yc[c2 * YPAD + pos] = *reinterpret_cast<const float2*>(mb + pos * 32 + c2 * 2);
    }
    __syncthreads();

    // ---- Phase 1: S = X X^T ----
    int lane = tid & 31, wg = tid >> 5;
    #pragma unroll 1
    for (int jp = 0; jp < 4; jp++) {
        int y0 = 64 * jp + 2 * lane;
        bool actv = (y0 < NPOS);
        int yc = actv ? y0 : 0;

        ull yc0[16], yc1[16];
        #pragma unroll
        for (int c2 = 0; c2 < 16; c2++) {
            ulonglong2 v = *reinterpret_cast<const ulonglong2*>(s_yc + c2 * YPAD + yc);
            yc0[c2] = v.x;
            yc1[c2] = v.y;
        }

        #pragma unroll 1
        for (int ix = 0; ix < 25; ix++) {
            int x = wg + 8 * ix;
            if (x >= NPOS) break;
            ull acc0 = 0ull, acc1 = 0ull;
            #pragma unroll
            for (int c2 = 0; c2 < 16; c2++) {
                ull w = *reinterpret_cast<const ull*>(s_yc + c2 * YPAD + x);  // broadcast
                acc0 = f2fma(w, yc0[c2], acc0);
                acc1 = f2fma(w, yc1[c2], acc1);
            }
            if (actv) {
                float2 r;
                r.x = f2sum(acc0);
                r.y = f2sum(acc1);
                *reinterpret_cast<float2*>(s_S + x * SROW + y0) = r;
            }
        }
    }
    __syncthreads();

    // ---- Phase 2: G[p,q] = sum over 25 diagonal shifts of S ----
    #pragma unroll 1
    for (int idx = tid; idx < PP * PP; idx += 256) {
        int p = idx / PP, q = idx - p * PP;
        int pr = p / 10, pc = p - pr * 10;
        int qr = q / 10, qc = q - qr * 10;
        int base = (pr * 14 + pc) * SROW + (qr * 14 + qc);
        float s = 0.f;
        #pragma unroll
        for (int i = 0; i < KS; i++)
            #pragma unroll
            for (int j = 0; j < KS; j++)
                s += s_S[base + (i * 14 + j) * (SROW + 1)];
        g_G[b * (PP * PP) + idx] = s;
    }
}

// ---------------- Kernel 4: expand Sigma_out (pure bandwidth) ----------------
__global__ __launch_bounds__(256) void k_expand(float* __restrict__ out) {
    __shared__ float  s_g[PP];
    __shared__ float4 s_sp[16];
    __shared__ float4 s_dv[16];

    int tid = threadIdx.x;
    int p = blockIdx.x, b = blockIdx.y;
    int bp = b * PP + p;

    if (tid < PP) s_g[tid] = g_G[b * (PP * PP) + p * PP + tid];
    if (tid >= 128 && tid < 144)
        s_sp[tid - 128] = *reinterpret_cast<const float4*>(g_sp + (tid - 128) * 4);
    if (tid >= 160 && tid < 176)
        s_dv[tid - 160] = *reinterpret_cast<const float4*>(g_dv + bp * KK + (tid - 160) * 4);
    __syncthreads();

    float* orow = out + BB * PP * KK + bp * (PP * KK);

    #pragma unroll
    for (int it = 0; it < 7; it++) {
        int v = tid + it * 256;
        if (v < PP * 16) {
            int q = v >> 4, kc = v & 15, k4 = kc * 4;
            float g = s_g[q];
            float4 sp = s_sp[kc];
            float4 r;
            r.x = sp.x * g; r.y = sp.y * g; r.z = sp.z * g; r.w = sp.w * g;
            if (q == p) {
                float4 dv = s_dv[kc];
                r.x += dv.x; r.y += dv.y; r.z += dv.z; r.w += dv.w;
            }
            r.x = isfinite(r.x) ? r.x : 0.f;
            r.y = isfinite(r.y) ? r.y : 0.f;
            r.z = isfinite(r.z) ? r.z : 0.f;
            r.w = isfinite(r.w) ? r.w : 0.f;
            if (q == k4)     r.x = fabsf(r.x);
            if (q == k4 + 1) r.y = fabsf(r.y);
            if (q == k4 + 2) r.z = fabsf(r.z);
            if (q == k4 + 3) r.w = fabsf(r.w);
            *reinterpret_cast<float4*>(orow + 4 * v) = r;
        }
    }
}

// ---------------- launch ----------------
extern "C" void kernel_launch(void* const* d_in, const int* in_sizes, int n_in,
                              void* d_out, int out_size) {
    const float* mu_in    = (const float*)d_in[0];
    const float* Sigma_in = (const float*)d_in[1];
    const float* w_mu     = (const float*)d_in[2];
    const float* w_sigma  = (const float*)d_in[3];
    float* out = (float*)d_out;

    const int GRAM_SMEM = NPOS * SROW * 4 + 16 * YPAD * 8;   // 180576 bytes
    cudaFuncSetAttribute(k_gram2, cudaFuncAttributeMaxDynamicSharedMemorySize, GRAM_SMEM);

    k_prep_w<<<401, 256>>>(w_mu, w_sigma);
    k_mu_diag<<<dim3(4, BB), 256>>>(mu_in, Sigma_in, out);
    k_gram2<<<BB, 256, GRAM_SMEM>>>(mu_in);
    k_expand<<<dim3(PP, BB), 256>>>(out);
}

// round 4
// speedup vs baseline: 1.6505x; 1.6505x over previous
#include <cuda_runtime.h>
#include <cuda_bf16.h>
#include <math.h>

// Problem constants
#define BB   32
#define HH   14
#define WW   14
#define CC   32
#define KK   64
#define KS   5
#define OH   10
#define OW   10
#define PP   100      // OH*OW
#define NPOS 196      // H*W
#define MM   800      // KS*KS*C
#define IMG  6272     // NPOS*CC floats per batch
#define SIGB 1229312  // NPOS*NPOS*CC floats per batch of Sigma_in
#define SIGR 6304     // NPOS*CC + CC (diag row stride in floats)

// Scratch (device globals)
__device__ float g_dv[BB * PP * KK];       // diag_vals
__device__ float g_G[BB * PP * PP];        // Gram matrices

// ---------------- f32x2 packed helpers ----------------
typedef unsigned long long ull;

__device__ __forceinline__ ull f2fma(ull a, ull b, ull c) {
    ull d;
    asm("fma.rn.f32x2 %0, %1, %2, %3;" : "=l"(d) : "l"(a), "l"(b), "l"(c));
    return d;
}
__device__ __forceinline__ ull f2mul(ull a, ull b) {
    ull d;
    asm("mul.rn.f32x2 %0, %1, %2;" : "=l"(d) : "l"(a), "l"(b));
    return d;
}
__device__ __forceinline__ ull f2pack(float lo, float hi) {
    ull d;
    asm("mov.b64 %0, {%1, %2};" : "=l"(d) : "f"(lo), "f"(hi));
    return d;
}
__device__ __forceinline__ float f2sum(ull v) {
    float lo, hi;
    asm("mov.b64 {%0, %1}, %2;" : "=f"(lo), "=f"(hi) : "l"(v));
    return lo + hi;
}

// ---------------- Kernel A: mu_out + diag_vals (fused gather, no prep) ----------------
// grid (4 ptiles, 32 b), 256 threads.
// R2 layout: k = tid&63 (consecutive within warp), pg = tid>>6 owns 7 p's.
__global__ __launch_bounds__(256) void k_mu_diag(const float* __restrict__ mu_in,
                                                 const float* __restrict__ Sg,
                                                 const float* __restrict__ w_mu,
                                                 const float* __restrict__ w_sigma,
                                                 float* __restrict__ out_mu) {
    __shared__ __align__(16) float s_mu[7 * 14 * 32];   // 3136
    __shared__ __align__(16) float s_ds[7 * 14 * 32];   // 3136
    __shared__ float s_S[7 * 14];                       // per-pos channel sums
    __shared__ float s_tr[25];

    int tid = threadIdx.x;
    int pt  = blockIdx.x;
    int b   = blockIdx.y;
    int r0  = (pt * 25) / 10;                // first image row of this tile

    // --- fused load: mu tile (coalesced) + Sigma-diag gather + channel sums ---
    {
        const float4* msrc = reinterpret_cast<const float4*>(mu_in + b * IMG + r0 * 448);
        const float*  sb   = Sg + b * SIGB;
        float4* mdst = reinterpret_cast<float4*>(s_mu);
        float4* ddst = reinterpret_cast<float4*>(s_ds);
        int c4 = tid & 7;
        #pragma unroll
        for (int it = 0; it < 4; it++) {
            int t = tid + it * 256;
            bool actv = (t < 784);
            int pos_l = t >> 3;                          // 0..97
            float4 sg = make_float4(0.f, 0.f, 0.f, 0.f);
            if (actv) {
                mdst[t] = msrc[t];
                int pos = r0 * 14 + pos_l;
                sg = *reinterpret_cast<const float4*>(sb + pos * SIGR + c4 * 4);
                ddst[t] = sg;
            }
            float part = sg.x + sg.y + sg.z + sg.w;
            part += __shfl_down_sync(0xffffffffu, part, 4, 8);
            part += __shfl_down_sync(0xffffffffu, part, 2, 8);
            part += __shfl_down_sync(0xffffffffu, part, 1, 8);
            if (actv && c4 == 0) s_S[pos_l] = part;
        }
    }
    __syncthreads();

    // --- trace per patch ---
    if (tid < 25) {
        int p  = pt * 25 + tid;
        int pr = p / 10 - r0, pc = p % 10;
        float s = 0.f;
        #pragma unroll
        for (int i = 0; i < KS; i++)
            #pragma unroll
            for (int j = 0; j < KS; j++)
                s += s_S[(pr + i) * 14 + pc + j];
        s_tr[tid] = s;
    }
    __syncthreads();

    int k  = tid & 63;
    int pg = tid >> 6;

    int prr[7], pcc[7];
    bool act[7];
    #pragma unroll
    for (int jj = 0; jj < 7; jj++) {
        int pl = pg * 7 + jj;
        act[jj] = (pl < 25);
        int plc = act[jj] ? pl : 24;
        int p = pt * 25 + plc;
        prr[jj] = p / 10 - r0;
        pcc[jj] = p % 10;
    }

    ull accM[7], accV[7];
    #pragma unroll
    for (int jj = 0; jj < 7; jj++) { accM[jj] = 0ull; accV[jj] = 0ull; }

    #pragma unroll 1
    for (int ij = 0; ij < 25; ij++) {
        int i = ij / 5, j = ij % 5;
        int posl[7];
        #pragma unroll
        for (int jj = 0; jj < 7; jj++)
            posl[jj] = ((prr[jj] + i) * 14 + pcc[jj] + j) * 32;
        const float* wbase = w_mu + ij * 32 * 64 + k;
        #pragma unroll
        for (int c4 = 0; c4 < 8; c4++) {
            // channels 4c4..4c4+3 of this (i,j): rows m0..m0+3 of w_mu at col k
            const float* wr = wbase + c4 * 4 * 64;
            float w0 = __ldg(wr);
            float w1 = __ldg(wr + 64);
            float w2 = __ldg(wr + 128);
            float w3 = __ldg(wr + 192);
            ull wA = f2pack(w0, w1);
            ull wB = f2pack(w2, w3);
            ull sA = f2mul(wA, wA);
            ull sB = f2mul(wB, wB);
            #pragma unroll
            for (int jj = 0; jj < 7; jj++) {
                ulonglong2 a = *reinterpret_cast<const ulonglong2*>(s_mu + posl[jj] + c4 * 4);
                ulonglong2 d = *reinterpret_cast<const ulonglong2*>(s_ds + posl[jj] + c4 * 4);
                accM[jj] = f2fma(a.x, wA, accM[jj]);
                accM[jj] = f2fma(a.y, wB, accM[jj]);
                accV[jj] = f2fma(d.x, sA, accV[jj]);
                accV[jj] = f2fma(d.y, sB, accV[jj]);
            }
        }
    }

    float spk = log1pf(expf(w_sigma[k]));
    #pragma unroll
    for (int jj = 0; jj < 7; jj++) {
        if (act[jj]) {
            int pl = pg * 7 + jj;
            int p  = pt * 25 + pl;
            out_mu[(b * PP + p) * KK + k] = f2sum(accM[jj]);
            g_dv[(b * PP + p) * KK + k]  = f2sum(accV[jj]) + spk * s_tr[pl];
        }
    }
}

// ---------------- Kernel B: Gram via position-Gram factorization ----------------
#define SROW 198
#define YPAD 198
__global__ __launch_bounds__(256) void k_gram2(const float* __restrict__ mu_in) {
    extern __shared__ float sm[];
    float*  s_S  = sm;                                    // [196][SROW]
    float2* s_yc = (float2*)(sm + NPOS * SROW);           // [16 c2][YPAD pos]

    int tid = threadIdx.x;
    int b   = blockIdx.x;
    const float* mb = mu_in + b * IMG;

    for (int t = tid; t < 16 * NPOS; t += 256) {
        int c2 = t & 15, pos = t >> 4;
        s_yc[c2 * YPAD + pos] = *reinterpret_cast<const float2*>(mb + pos * 32 + c2 * 2);
    }
    __syncthreads();

    // ---- Phase 1: S = X X^T ----
    int lane = tid & 31, wg = tid >> 5;
    #pragma unroll 1
    for (int jp = 0; jp < 4; jp++) {
        int y0 = 64 * jp + 2 * lane;
        bool actv = (y0 < NPOS);
        int yc = actv ? y0 : 0;

        ull yc0[16], yc1[16];
        #pragma unroll
        for (int c2 = 0; c2 < 16; c2++) {
            ulonglong2 v = *reinterpret_cast<const ulonglong2*>(s_yc + c2 * YPAD + yc);
            yc0[c2] = v.x;
            yc1[c2] = v.y;
        }

        #pragma unroll 1
        for (int ix = 0; ix < 25; ix++) {
            int x = wg + 8 * ix;
            if (x >= NPOS) break;
            ull acc0 = 0ull, acc1 = 0ull;
            #pragma unroll
            for (int c2 = 0; c2 < 16; c2++) {
                ull w = *reinterpret_cast<const ull*>(s_yc + c2 * YPAD + x);  // broadcast
                acc0 = f2fma(w, yc0[c2], acc0);
                acc1 = f2fma(w, yc1[c2], acc1);
            }
            if (actv) {
                float2 r;
                r.x = f2sum(acc0);
                r.y = f2sum(acc1);
                *reinterpret_cast<float2*>(s_S + x * SROW + y0) = r;
            }
        }
    }
    __syncthreads();

    // ---- Phase 2: G[p,q] = sum over 25 diagonal shifts of S ----
    #pragma unroll 1
    for (int idx = tid; idx < PP * PP; idx += 256) {
        int p = idx / PP, q = idx - p * PP;
        int pr = p / 10, pc = p - pr * 10;
        int qr = q / 10, qc = q - qr * 10;
        int base = (pr * 14 + pc) * SROW + (qr * 14 + qc);
        float s = 0.f;
        #pragma unroll
        for (int i = 0; i < KS; i++)
            #pragma unroll
            for (int j = 0; j < KS; j++)
                s += s_S[base + (i * 14 + j) * (SROW + 1)];
        g_G[b * (PP * PP) + idx] = s;
    }
}

// ---------------- Kernel C: expand Sigma_out (pure bandwidth) ----------------
__global__ __launch_bounds__(256) void k_expand(const float* __restrict__ w_sigma,
                                                float* __restrict__ out) {
    __shared__ float  s_g[PP];
    __shared__ float4 s_sp[16];
    __shared__ float4 s_dv[16];

    int tid = threadIdx.x;
    int p = blockIdx.x, b = blockIdx.y;
    int bp = b * PP + p;

    if (tid < PP) s_g[tid] = g_G[b * (PP * PP) + p * PP + tid];
    if (tid >= 128 && tid < 144) {
        int k4 = (tid - 128) * 4;
        float4 sp;
        sp.x = log1pf(expf(w_sigma[k4]));
        sp.y = log1pf(expf(w_sigma[k4 + 1]));
        sp.z = log1pf(expf(w_sigma[k4 + 2]));
        sp.w = log1pf(expf(w_sigma[k4 + 3]));
        s_sp[tid - 128] = sp;
    }
    if (tid >= 160 && tid < 176)
        s_dv[tid - 160] = *reinterpret_cast<const float4*>(g_dv + bp * KK + (tid - 160) * 4);
    __syncthreads();

    float* orow = out + BB * PP * KK + bp * (PP * KK);

    #pragma unroll
    for (int it = 0; it < 7; it++) {
        int v = tid + it * 256;
        if (v < PP * 16) {
            int q = v >> 4, kc = v & 15, k4 = kc * 4;
            float g = s_g[q];
            float4 sp = s_sp[kc];
            float4 r;
            r.x = sp.x * g; r.y = sp.y * g; r.z = sp.z * g; r.w = sp.w * g;
            if (q == p) {
                float4 dv = s_dv[kc];
                r.x += dv.x; r.y += dv.y; r.z += dv.z; r.w += dv.w;
            }
            r.x = isfinite(r.x) ? r.x : 0.f;
            r.y = isfinite(r.y) ? r.y : 0.f;
            r.z = isfinite(r.z) ? r.z : 0.f;
            r.w = isfinite(r.w) ? r.w : 0.f;
            if (q == k4)     r.x = fabsf(r.x);
            if (q == k4 + 1) r.y = fabsf(r.y);
            if (q == k4 + 2) r.z = fabsf(r.z);
            if (q == k4 + 3) r.w = fabsf(r.w);
            *reinterpret_cast<float4*>(orow + 4 * v) = r;
        }
    }
}

// ---------------- launch ----------------
extern "C" void kernel_launch(void* const* d_in, const int* in_sizes, int n_in,
                              void* d_out, int out_size) {
    const float* mu_in    = (const float*)d_in[0];
    const float* Sigma_in = (const float*)d_in[1];
    const float* w_mu     = (const float*)d_in[2];
    const float* w_sigma  = (const float*)d_in[3];
    float* out = (float*)d_out;

    const int GRAM_SMEM = NPOS * SROW * 4 + 16 * YPAD * 8;   // 180576 bytes
    cudaFuncSetAttribute(k_gram2, cudaFuncAttributeMaxDynamicSharedMemorySize, GRAM_SMEM);

    // Fork: gram2 (independent of mu_diag) runs concurrently on a side stream.
    static cudaStream_t s2 = nullptr;
    static cudaEvent_t  eFork = nullptr, eJoin = nullptr;
    if (s2 == nullptr) {
        cudaStreamCreateWithFlags(&s2, cudaStreamNonBlocking);
        cudaEventCreateWithFlags(&eFork, cudaEventDisableTiming);
        cudaEventCreateWithFlags(&eJoin, cudaEventDisableTiming);
    }

    cudaEventRecord(eFork, 0);
    cudaStreamWaitEvent(s2, eFork, 0);
    k_gram2<<<BB, 256, GRAM_SMEM, s2>>>(mu_in);
    cudaEventRecord(eJoin, s2);

    k_mu_diag<<<dim3(4, BB), 256>>>(mu_in, Sigma_in, w_mu, w_sigma, out);

    cudaStreamWaitEvent(0, eJoin, 0);
    k_expand<<<dim3(PP, BB), 256>>>(w_sigma, out);
}